// round 1
// baseline (speedup 1.0000x reference)
#include <cuda_runtime.h>
#include <cstdint>

#define NMAX 100000
#define EMAX 1000000
#define HDIM 64
#define PCOLS 256   // NB * H

// ---------------- scratch (device globals; no allocation allowed) ----------------
__device__ float g_h0[(size_t)NMAX * HDIM];
__device__ float g_p[(size_t)NMAX * PCOLS];
__device__ float g_accA[(size_t)NMAX * HDIM];
__device__ float g_accB[(size_t)NMAX * HDIM];
__device__ float g_sum[HDIM];
__device__ int   g_max[HDIM];

// ---------------- input projection: h0 = x @ W_in + b_in  (N x 15 @ 15 x 64) ----
__global__ __launch_bounds__(256) void input_proj(const float* __restrict__ x,
                                                  const float* __restrict__ Win,
                                                  const float* __restrict__ bin,
                                                  float* __restrict__ h0, int N) {
    __shared__ float sW[15 * 64];
    __shared__ float sx[4][15];
    int tid = threadIdx.x;
    for (int i = tid; i < 15 * 64; i += 256) sW[i] = Win[i];
    int n0 = blockIdx.x * 4;
    if (tid < 60) {
        int r = tid / 15, c = tid % 15;
        int n = n0 + r;
        sx[r][c] = (n < N) ? x[n * 15 + c] : 0.f;
    }
    __syncthreads();
    int r = tid >> 6, j = tid & 63;
    int n = n0 + r;
    if (n < N) {
        float acc = bin[j];
#pragma unroll
        for (int k = 0; k < 15; k++) acc += sx[r][k] * sW[k * 64 + j];
        h0[(size_t)n * 64 + j] = acc;
    }
}

// ---------------- generic 64-wide GEMM: C[:,0:64] = act(A) @ Wview + bias -------
// A: N x 64 row-major. W: 64 x 64 view with row stride ldW. C row stride ldC.
__global__ __launch_bounds__(256) void gemm64(const float* __restrict__ A, int relu_in,
                                              const float* __restrict__ W, int ldW,
                                              const float* __restrict__ bias,
                                              float* __restrict__ C, int ldC, int N) {
    __shared__ float As[64][68];      // padded rows: conflict-free column reads
    __shared__ float Bs[64 * 64];
    int tid = threadIdx.x;
    int row0 = blockIdx.x * 64;

    // load A tile (apply input relu), zero-pad tail rows
#pragma unroll
    for (int i = 0; i < 4; i++) {
        int idx = tid + i * 256;          // float4 index over 64x16
        int r = idx >> 4, c4 = idx & 15;
        float4 v = make_float4(0.f, 0.f, 0.f, 0.f);
        int n = row0 + r;
        if (n < N) v = *(const float4*)(A + (size_t)n * 64 + c4 * 4);
        if (relu_in) {
            v.x = fmaxf(v.x, 0.f); v.y = fmaxf(v.y, 0.f);
            v.z = fmaxf(v.z, 0.f); v.w = fmaxf(v.w, 0.f);
        }
        *(float4*)(&As[r][c4 * 4]) = v;
    }
    // load W tile
#pragma unroll
    for (int i = 0; i < 4; i++) {
        int idx = tid + i * 256;
        int k = idx >> 4, c4 = idx & 15;
        float4 v = *(const float4*)(W + (size_t)k * ldW + c4 * 4);
        *(float4*)(&Bs[k * 64 + c4 * 4]) = v;
    }
    __syncthreads();

    int tx = tid & 15, ty = tid >> 4;
    int r0 = ty * 4, c0 = tx * 4;
    float acc00=0,acc01=0,acc02=0,acc03=0, acc10=0,acc11=0,acc12=0,acc13=0;
    float acc20=0,acc21=0,acc22=0,acc23=0, acc30=0,acc31=0,acc32=0,acc33=0;
#pragma unroll 16
    for (int k = 0; k < 64; k++) {
        float4 b4 = *(const float4*)(&Bs[k * 64 + c0]);
        float a0 = As[r0 + 0][k], a1 = As[r0 + 1][k];
        float a2 = As[r0 + 2][k], a3 = As[r0 + 3][k];
        acc00 += a0*b4.x; acc01 += a0*b4.y; acc02 += a0*b4.z; acc03 += a0*b4.w;
        acc10 += a1*b4.x; acc11 += a1*b4.y; acc12 += a1*b4.z; acc13 += a1*b4.w;
        acc20 += a2*b4.x; acc21 += a2*b4.y; acc22 += a2*b4.z; acc23 += a2*b4.w;
        acc30 += a3*b4.x; acc31 += a3*b4.y; acc32 += a3*b4.z; acc33 += a3*b4.w;
    }
    float4 bb = make_float4(0.f, 0.f, 0.f, 0.f);
    if (bias) bb = *(const float4*)(bias + c0);
    float4 o;
    int n;
    n = row0 + r0 + 0; if (n < N) { o = make_float4(acc00+bb.x, acc01+bb.y, acc02+bb.z, acc03+bb.w); *(float4*)(C + (size_t)n*ldC + c0) = o; }
    n = row0 + r0 + 1; if (n < N) { o = make_float4(acc10+bb.x, acc11+bb.y, acc12+bb.z, acc13+bb.w); *(float4*)(C + (size_t)n*ldC + c0) = o; }
    n = row0 + r0 + 2; if (n < N) { o = make_float4(acc20+bb.x, acc21+bb.y, acc22+bb.z, acc23+bb.w); *(float4*)(C + (size_t)n*ldC + c0) = o; }
    n = row0 + r0 + 3; if (n < N) { o = make_float4(acc30+bb.x, acc31+bb.y, acc32+bb.z, acc33+bb.w); *(float4*)(C + (size_t)n*ldC + c0) = o; }
}

// ---------------- edge scatter: acc[tgt] += sum_b coeffs[et][b] * p[src][b*64:] --
__global__ __launch_bounds__(256) void edge_scatter(const int* __restrict__ src,
                                                    const int* __restrict__ tgt,
                                                    const int* __restrict__ et,
                                                    const float* __restrict__ coeffs,
                                                    const float* __restrict__ p,
                                                    float* __restrict__ acc, int E) {
    int e = blockIdx.x * 16 + (threadIdx.x >> 4);
    int lane = threadIdx.x & 15;
    if (e >= E) return;
    int s = src[e], t = tgt[e], r = et[e];
    float4 c = *(const float4*)(coeffs + r * 4);
    const float4* ps = (const float4*)(p + (size_t)s * PCOLS);
    float4 p0 = ps[lane], p1 = ps[16 + lane], p2 = ps[32 + lane], p3 = ps[48 + lane];
    float4 m;
    m.x = c.x*p0.x + c.y*p1.x + c.z*p2.x + c.w*p3.x;
    m.y = c.x*p0.y + c.y*p1.y + c.z*p2.y + c.w*p3.y;
    m.z = c.x*p0.z + c.y*p1.z + c.z*p2.z + c.w*p3.z;
    m.w = c.x*p0.w + c.y*p1.w + c.z*p2.w + c.w*p3.w;
    float* dst = acc + (size_t)t * 64 + lane * 4;
    asm volatile("red.global.add.v4.f32 [%0], {%1,%2,%3,%4};"
                 :: "l"(dst), "f"(m.x), "f"(m.y), "f"(m.z), "f"(m.w) : "memory");
}

// ---------------- readout reductions --------------------------------------------
__global__ void zero_stats() {
    int j = threadIdx.x;
    if (j < HDIM) { g_sum[j] = 0.f; g_max[j] = 0; }
}

__global__ __launch_bounds__(256) void reduce_stats(const float* __restrict__ acc, int N) {
    int j = threadIdx.x & 63;
    int rl = threadIdx.x >> 6;                   // 0..3
    float s = 0.f, mx = 0.f;
    for (int n = blockIdx.x * 4 + rl; n < N; n += gridDim.x * 4) {
        float v = fmaxf(acc[(size_t)n * 64 + j], 0.f);
        s += v; mx = fmaxf(mx, v);
    }
    __shared__ float ss[4][64];
    __shared__ float sm[4][64];
    ss[rl][j] = s; sm[rl][j] = mx;
    __syncthreads();
    if (rl == 0) {
        s  = ss[0][j] + ss[1][j] + ss[2][j] + ss[3][j];
        mx = fmaxf(fmaxf(sm[0][j], sm[1][j]), fmaxf(sm[2][j], sm[3][j]));
        atomicAdd(&g_sum[j], s);
        atomicMax(&g_max[j], __float_as_int(mx));  // valid: relu => all >= 0
    }
}

__global__ void graph_head(const float* __restrict__ Wr1, const float* __restrict__ br1,
                           const float* __restrict__ Wr2, const float* __restrict__ br2,
                           float* __restrict__ out, int N) {
    __shared__ float g[128];
    __shared__ float t[64];
    int tid = threadIdx.x;   // 128 threads
    if (tid < 64) g[tid] = g_sum[tid] / (float)N;
    else          g[tid] = __int_as_float(g_max[tid - 64]);
    __syncthreads();
    if (tid < 64) {
        float a = br1[tid];
#pragma unroll 8
        for (int k = 0; k < 128; k++) a += g[k] * Wr1[k * 64 + tid];
        t[tid] = fmaxf(a, 0.f);
    }
    __syncthreads();
    float a = br2[tid];
#pragma unroll 8
    for (int k = 0; k < 64; k++) a += t[k] * Wr2[k * 128 + tid];
    out[tid] = a;
}

// ---------------- launcher -------------------------------------------------------
extern "C" void kernel_launch(void* const* d_in, const int* in_sizes, int n_in,
                              void* d_out, int out_size) {
    const float* x      = (const float*)d_in[0];
    const int*   eidx   = (const int*)  d_in[1];
    const int*   et     = (const int*)  d_in[2];
    const float* Win    = (const float*)d_in[3];
    const float* bin    = (const float*)d_in[4];
    const float* Wself0 = (const float*)d_in[5];
    const float* bself0 = (const float*)d_in[6];
    const float* bases0 = (const float*)d_in[7];
    const float* coef0  = (const float*)d_in[8];
    const float* Wself1 = (const float*)d_in[9];
    const float* bself1 = (const float*)d_in[10];
    const float* bases1 = (const float*)d_in[11];
    const float* coef1  = (const float*)d_in[12];
    const float* Wr1    = (const float*)d_in[13];
    const float* br1    = (const float*)d_in[14];
    const float* Wr2    = (const float*)d_in[15];
    const float* br2    = (const float*)d_in[16];
    const float* Wnp    = (const float*)d_in[17];
    const float* bnp    = (const float*)d_in[18];
    float* out = (float*)d_out;

    int N = in_sizes[0] / 15;
    int E = in_sizes[2];
    const int* src = eidx;
    const int* tgt = eidx + E;

    float *h0, *p, *accA, *accB;
    cudaGetSymbolAddress((void**)&h0,   g_h0);
    cudaGetSymbolAddress((void**)&p,    g_p);
    cudaGetSymbolAddress((void**)&accA, g_accA);
    cudaGetSymbolAddress((void**)&accB, g_accB);

    int gemm_blocks = (N + 63) / 64;
    int edge_blocks = (E + 15) / 16;

    // h0 = x @ Win + bin
    input_proj<<<(N + 3) / 4, 256>>>(x, Win, bin, h0, N);

    // ---- layer 0 ----
    gemm64<<<gemm_blocks, 256>>>(h0, 0, Wself0, 64, bself0, accA, 64, N);
    for (int b = 0; b < 4; b++)
        gemm64<<<gemm_blocks, 256>>>(h0, 0, bases0 + (size_t)b * 64 * 64, 64, nullptr,
                                     p + b * 64, PCOLS, N);
    edge_scatter<<<edge_blocks, 256>>>(src, tgt, et, coef0, p, accA, E);

    // ---- layer 1 (input = relu(accA)) ----
    gemm64<<<gemm_blocks, 256>>>(accA, 1, Wself1, 64, bself1, accB, 64, N);
    for (int b = 0; b < 4; b++)
        gemm64<<<gemm_blocks, 256>>>(accA, 1, bases1 + (size_t)b * 64 * 64, 64, nullptr,
                                     p + b * 64, PCOLS, N);
    edge_scatter<<<edge_blocks, 256>>>(src, tgt, et, coef1, p, accB, E);

    // ---- readout (on relu(accB)) ----
    zero_stats<<<1, 64>>>();
    reduce_stats<<<148, 256>>>(accB, N);
    graph_head<<<1, 128>>>(Wr1, br1, Wr2, br2, out, N);

    // ---- node embeddings: out[128 + n*128 + j] = relu(accB) @ Wnp + bnp ----
    for (int half = 0; half < 2; half++)
        gemm64<<<gemm_blocks, 256>>>(accB, 1, Wnp + half * 64, 128, bnp + half * 64,
                                     out + 128 + half * 64, 128, N);
}

// round 3
// speedup vs baseline: 1.1786x; 1.1786x over previous
#include <cuda_runtime.h>
#include <cstdint>

#define NMAX 100000
#define EMAX 1000000
#define HDIM 64
#define PCOLS 256   // NB * H

// ---------------- scratch (device globals; no allocation allowed) ----------------
__device__ float g_h0[(size_t)NMAX * HDIM];
__device__ float g_p[(size_t)NMAX * PCOLS];
__device__ float g_accA[(size_t)NMAX * HDIM];
__device__ float g_accB[(size_t)NMAX * HDIM];
__device__ float g_sum[HDIM];
__device__ int   g_max[HDIM];
// sort scratch
__device__ int g_cnt[NMAX];
__device__ int g_off[NMAX];
__device__ int g_cursor[NMAX];
__device__ int g_bsum[1024];
__device__ int g_perm[EMAX];

// ---------------- input projection: h0 = x @ W_in + b_in  (N x 15 @ 15 x 64) ----
__global__ __launch_bounds__(256) void input_proj(const float* __restrict__ x,
                                                  const float* __restrict__ Win,
                                                  const float* __restrict__ bin,
                                                  float* __restrict__ h0, int N) {
    __shared__ float sW[15 * 64];
    __shared__ float sx[4][15];
    int tid = threadIdx.x;
    for (int i = tid; i < 15 * 64; i += 256) sW[i] = Win[i];
    int n0 = blockIdx.x * 4;
    if (tid < 60) {
        int r = tid / 15, c = tid % 15;
        int n = n0 + r;
        sx[r][c] = (n < N) ? x[n * 15 + c] : 0.f;
    }
    __syncthreads();
    int r = tid >> 6, j = tid & 63;
    int n = n0 + r;
    if (n < N) {
        float acc = bin[j];
#pragma unroll
        for (int k = 0; k < 15; k++) acc += sx[r][k] * sW[k * 64 + j];
        h0[(size_t)n * 64 + j] = acc;
    }
}

// ---------------- fused RGCN GEMM: [self | p0..p3] = act(A) @ [Wself|B0..B3] -----
// Dynamic smem: As[64][68] + Ws[5][64*64]  (99328 bytes)
__global__ __launch_bounds__(256) void rgcn_fused(const float* __restrict__ A, int relu_in,
                                                  const float* __restrict__ Wself,
                                                  const float* __restrict__ bases,
                                                  const float* __restrict__ bias,
                                                  float* __restrict__ Cself,
                                                  float* __restrict__ P, int N) {
    extern __shared__ float sm[];
    float (*As)[68] = (float(*)[68])sm;
    float* Ws = sm + 64 * 68;
    int tid = threadIdx.x;
    int row0 = blockIdx.x * 64;

    // load A tile (apply input relu), zero-pad tail rows
#pragma unroll
    for (int i = 0; i < 4; i++) {
        int idx = tid + i * 256;          // float4 index over 64x16
        int r = idx >> 4, c4 = idx & 15;
        float4 v = make_float4(0.f, 0.f, 0.f, 0.f);
        int n = row0 + r;
        if (n < N) v = *(const float4*)(A + (size_t)n * 64 + c4 * 4);
        if (relu_in) {
            v.x = fmaxf(v.x, 0.f); v.y = fmaxf(v.y, 0.f);
            v.z = fmaxf(v.z, 0.f); v.w = fmaxf(v.w, 0.f);
        }
        *(float4*)(&As[r][c4 * 4]) = v;
    }
    // load 5 weight matrices: Ws[0]=Wself, Ws[1..4]=bases
#pragma unroll
    for (int i = 0; i < 20; i++) {
        int idx = tid + i * 256;      // float4 index, 5120 total
        float4 v;
        if (idx < 1024) v = *(const float4*)(Wself + idx * 4);
        else            v = *(const float4*)(bases + (size_t)(idx - 1024) * 4);
        *(float4*)(&Ws[idx * 4]) = v;
    }
    __syncthreads();

    int tx = tid & 15, ty = tid >> 4;
    int r0 = ty * 4, c0 = tx * 4;
    float acc[5][16];
#pragma unroll
    for (int m = 0; m < 5; m++)
#pragma unroll
        for (int i = 0; i < 16; i++) acc[m][i] = 0.f;

#pragma unroll 4
    for (int k = 0; k < 64; k++) {
        float a0 = As[r0 + 0][k], a1 = As[r0 + 1][k];
        float a2 = As[r0 + 2][k], a3 = As[r0 + 3][k];
#pragma unroll
        for (int m = 0; m < 5; m++) {
            float4 b = *(const float4*)(&Ws[m * 4096 + k * 64 + c0]);
            acc[m][0]  += a0 * b.x; acc[m][1]  += a0 * b.y; acc[m][2]  += a0 * b.z; acc[m][3]  += a0 * b.w;
            acc[m][4]  += a1 * b.x; acc[m][5]  += a1 * b.y; acc[m][6]  += a1 * b.z; acc[m][7]  += a1 * b.w;
            acc[m][8]  += a2 * b.x; acc[m][9]  += a2 * b.y; acc[m][10] += a2 * b.z; acc[m][11] += a2 * b.w;
            acc[m][12] += a3 * b.x; acc[m][13] += a3 * b.y; acc[m][14] += a3 * b.z; acc[m][15] += a3 * b.w;
        }
    }

    float4 bb = *(const float4*)(bias + c0);
#pragma unroll
    for (int r = 0; r < 4; r++) {
        int n = row0 + r0 + r;
        if (n >= N) continue;
        float4 o = make_float4(acc[0][r*4+0] + bb.x, acc[0][r*4+1] + bb.y,
                               acc[0][r*4+2] + bb.z, acc[0][r*4+3] + bb.w);
        *(float4*)(Cself + (size_t)n * 64 + c0) = o;
#pragma unroll
        for (int m = 1; m < 5; m++) {
            float4 q = make_float4(acc[m][r*4+0], acc[m][r*4+1], acc[m][r*4+2], acc[m][r*4+3]);
            *(float4*)(P + (size_t)n * PCOLS + (m - 1) * 64 + c0) = q;
        }
    }
}

// ---------------- generic 64-wide GEMM (for node-emb): C = relu(A) @ Wview + b --
__global__ __launch_bounds__(256) void gemm64(const float* __restrict__ A, int relu_in,
                                              const float* __restrict__ W, int ldW,
                                              const float* __restrict__ bias,
                                              float* __restrict__ C, int ldC, int N) {
    __shared__ float As[64][68];
    __shared__ float Bs[64 * 64];
    int tid = threadIdx.x;
    int row0 = blockIdx.x * 64;
#pragma unroll
    for (int i = 0; i < 4; i++) {
        int idx = tid + i * 256;
        int r = idx >> 4, c4 = idx & 15;
        float4 v = make_float4(0.f, 0.f, 0.f, 0.f);
        int n = row0 + r;
        if (n < N) v = *(const float4*)(A + (size_t)n * 64 + c4 * 4);
        if (relu_in) {
            v.x = fmaxf(v.x, 0.f); v.y = fmaxf(v.y, 0.f);
            v.z = fmaxf(v.z, 0.f); v.w = fmaxf(v.w, 0.f);
        }
        *(float4*)(&As[r][c4 * 4]) = v;
    }
#pragma unroll
    for (int i = 0; i < 4; i++) {
        int idx = tid + i * 256;
        int k = idx >> 4, c4 = idx & 15;
        float4 v = *(const float4*)(W + (size_t)k * ldW + c4 * 4);
        *(float4*)(&Bs[k * 64 + c4 * 4]) = v;
    }
    __syncthreads();

    int tx = tid & 15, ty = tid >> 4;
    int r0 = ty * 4, c0 = tx * 4;
    float acc00=0,acc01=0,acc02=0,acc03=0, acc10=0,acc11=0,acc12=0,acc13=0;
    float acc20=0,acc21=0,acc22=0,acc23=0, acc30=0,acc31=0,acc32=0,acc33=0;
#pragma unroll 16
    for (int k = 0; k < 64; k++) {
        float4 b4 = *(const float4*)(&Bs[k * 64 + c0]);
        float a0 = As[r0 + 0][k], a1 = As[r0 + 1][k];
        float a2 = As[r0 + 2][k], a3 = As[r0 + 3][k];
        acc00 += a0*b4.x; acc01 += a0*b4.y; acc02 += a0*b4.z; acc03 += a0*b4.w;
        acc10 += a1*b4.x; acc11 += a1*b4.y; acc12 += a1*b4.z; acc13 += a1*b4.w;
        acc20 += a2*b4.x; acc21 += a2*b4.y; acc22 += a2*b4.z; acc23 += a2*b4.w;
        acc30 += a3*b4.x; acc31 += a3*b4.y; acc32 += a3*b4.z; acc33 += a3*b4.w;
    }
    float4 bb = make_float4(0.f, 0.f, 0.f, 0.f);
    if (bias) bb = *(const float4*)(bias + c0);
    float4 o;
    int n;
    n = row0 + r0 + 0; if (n < N) { o = make_float4(acc00+bb.x, acc01+bb.y, acc02+bb.z, acc03+bb.w); *(float4*)(C + (size_t)n*ldC + c0) = o; }
    n = row0 + r0 + 1; if (n < N) { o = make_float4(acc10+bb.x, acc11+bb.y, acc12+bb.z, acc13+bb.w); *(float4*)(C + (size_t)n*ldC + c0) = o; }
    n = row0 + r0 + 2; if (n < N) { o = make_float4(acc20+bb.x, acc21+bb.y, acc22+bb.z, acc23+bb.w); *(float4*)(C + (size_t)n*ldC + c0) = o; }
    n = row0 + r0 + 3; if (n < N) { o = make_float4(acc30+bb.x, acc31+bb.y, acc32+bb.z, acc33+bb.w); *(float4*)(C + (size_t)n*ldC + c0) = o; }
}

// ---------------- counting sort of edges by src --------------------------------
__global__ void zero_cnt(int* cnt, int N) {
    int i = blockIdx.x * blockDim.x + threadIdx.x;
    if (i < N) cnt[i] = 0;
}
__global__ void hist(const int* __restrict__ src, int* cnt, int E) {
    int e = blockIdx.x * blockDim.x + threadIdx.x;
    if (e < E) atomicAdd(&cnt[src[e]], 1);
}
__global__ __launch_bounds__(1024) void scanA(const int* __restrict__ cnt, int* off,
                                              int* bsum, int N) {
    __shared__ int s[1024];
    int i = blockIdx.x * 1024 + threadIdx.x;
    int v = (i < N) ? cnt[i] : 0;
    s[threadIdx.x] = v;
    __syncthreads();
#pragma unroll
    for (int d = 1; d < 1024; d <<= 1) {
        int t = (threadIdx.x >= d) ? s[threadIdx.x - d] : 0;
        __syncthreads();
        s[threadIdx.x] += t;
        __syncthreads();
    }
    if (i < N) off[i] = s[threadIdx.x] - v;   // exclusive
    if (threadIdx.x == 1023) bsum[blockIdx.x] = s[1023];
}
__global__ __launch_bounds__(1024) void scanB(int* bsum, int nchunks) {
    __shared__ int s[1024];
    int v = (threadIdx.x < nchunks) ? bsum[threadIdx.x] : 0;
    s[threadIdx.x] = v;
    __syncthreads();
#pragma unroll
    for (int d = 1; d < 1024; d <<= 1) {
        int t = (threadIdx.x >= d) ? s[threadIdx.x - d] : 0;
        __syncthreads();
        s[threadIdx.x] += t;
        __syncthreads();
    }
    if (threadIdx.x < nchunks) bsum[threadIdx.x] = s[threadIdx.x] - v;  // exclusive
}
__global__ __launch_bounds__(1024) void scanC(int* off, const int* __restrict__ bsum,
                                              int* cursor, int N) {
    int i = blockIdx.x * 1024 + threadIdx.x;
    if (i < N) {
        int o = off[i] + bsum[blockIdx.x];
        off[i] = o;
        cursor[i] = o;
    }
}
__global__ void permute(const int* __restrict__ src, int* cursor, int* perm, int E) {
    int e = blockIdx.x * blockDim.x + threadIdx.x;
    if (e < E) {
        int pos = atomicAdd(&cursor[src[e]], 1);
        perm[pos] = e;
    }
}

// ---------------- edge aggregate: one 16-thread group per source node -----------
__global__ __launch_bounds__(256) void edge_agg(const int* __restrict__ off,
                                                const int* __restrict__ perm,
                                                const int* __restrict__ tgt,
                                                const int* __restrict__ et,
                                                const float* __restrict__ coeffs,
                                                const float* __restrict__ p,
                                                float* __restrict__ acc, int N, int E) {
    int g = blockIdx.x * 16 + (threadIdx.x >> 4);
    int lane = threadIdx.x & 15;
    if (g >= N) return;
    int beg = off[g];
    int end = (g + 1 < N) ? off[g + 1] : E;
    if (beg == end) return;
    const float4* ps = (const float4*)(p + (size_t)g * PCOLS);
    float4 p0 = ps[lane], p1 = ps[16 + lane], p2 = ps[32 + lane], p3 = ps[48 + lane];
    for (int i = beg; i < end; i++) {
        int e = perm[i];
        int t = tgt[e], r = et[e];
        float4 c = *(const float4*)(coeffs + r * 4);
        float4 m;
        m.x = c.x*p0.x + c.y*p1.x + c.z*p2.x + c.w*p3.x;
        m.y = c.x*p0.y + c.y*p1.y + c.z*p2.y + c.w*p3.y;
        m.z = c.x*p0.z + c.y*p1.z + c.z*p2.z + c.w*p3.z;
        m.w = c.x*p0.w + c.y*p1.w + c.z*p2.w + c.w*p3.w;
        float* dst = acc + (size_t)t * 64 + lane * 4;
        asm volatile("red.global.add.v4.f32 [%0], {%1,%2,%3,%4};"
                     :: "l"(dst), "f"(m.x), "f"(m.y), "f"(m.z), "f"(m.w) : "memory");
    }
}

// ---------------- readout reductions --------------------------------------------
__global__ void zero_stats() {
    int j = threadIdx.x;
    if (j < HDIM) { g_sum[j] = 0.f; g_max[j] = 0; }
}

__global__ __launch_bounds__(256) void reduce_stats(const float* __restrict__ acc, int N) {
    int j = threadIdx.x & 63;
    int rl = threadIdx.x >> 6;
    float s = 0.f, mx = 0.f;
    for (int n = blockIdx.x * 4 + rl; n < N; n += gridDim.x * 4) {
        float v = fmaxf(acc[(size_t)n * 64 + j], 0.f);
        s += v; mx = fmaxf(mx, v);
    }
    __shared__ float ss[4][64];
    __shared__ float sm[4][64];
    ss[rl][j] = s; sm[rl][j] = mx;
    __syncthreads();
    if (rl == 0) {
        s  = ss[0][j] + ss[1][j] + ss[2][j] + ss[3][j];
        mx = fmaxf(fmaxf(sm[0][j], sm[1][j]), fmaxf(sm[2][j], sm[3][j]));
        atomicAdd(&g_sum[j], s);
        atomicMax(&g_max[j], __float_as_int(mx));
    }
}

__global__ void graph_head(const float* __restrict__ Wr1, const float* __restrict__ br1,
                           const float* __restrict__ Wr2, const float* __restrict__ br2,
                           float* __restrict__ out, int N) {
    __shared__ float g[128];
    __shared__ float t[64];
    int tid = threadIdx.x;
    if (tid < 64) g[tid] = g_sum[tid] / (float)N;
    else          g[tid] = __int_as_float(g_max[tid - 64]);
    __syncthreads();
    if (tid < 64) {
        float a = br1[tid];
#pragma unroll 8
        for (int k = 0; k < 128; k++) a += g[k] * Wr1[k * 64 + tid];
        t[tid] = fmaxf(a, 0.f);
    }
    __syncthreads();
    float a = br2[tid];
#pragma unroll 8
    for (int k = 0; k < 64; k++) a += t[k] * Wr2[k * 128 + tid];
    out[tid] = a;
}

// ---------------- launcher -------------------------------------------------------
extern "C" void kernel_launch(void* const* d_in, const int* in_sizes, int n_in,
                              void* d_out, int out_size) {
    const float* x      = (const float*)d_in[0];
    const int*   eidx   = (const int*)  d_in[1];
    const int*   et     = (const int*)  d_in[2];
    const float* Win    = (const float*)d_in[3];
    const float* bin    = (const float*)d_in[4];
    const float* Wself0 = (const float*)d_in[5];
    const float* bself0 = (const float*)d_in[6];
    const float* bases0 = (const float*)d_in[7];
    const float* coef0  = (const float*)d_in[8];
    const float* Wself1 = (const float*)d_in[9];
    const float* bself1 = (const float*)d_in[10];
    const float* bases1 = (const float*)d_in[11];
    const float* coef1  = (const float*)d_in[12];
    const float* Wr1    = (const float*)d_in[13];
    const float* br1    = (const float*)d_in[14];
    const float* Wr2    = (const float*)d_in[15];
    const float* br2    = (const float*)d_in[16];
    const float* Wnp    = (const float*)d_in[17];
    const float* bnp    = (const float*)d_in[18];
    float* out = (float*)d_out;

    int N = in_sizes[0] / 15;
    int E = in_sizes[2];
    const int* src = eidx;
    const int* tgt = eidx + E;

    float *h0, *p, *accA, *accB;
    int *cnt, *off, *cursor, *bsum, *perm;
    cudaGetSymbolAddress((void**)&h0,     g_h0);
    cudaGetSymbolAddress((void**)&p,      g_p);
    cudaGetSymbolAddress((void**)&accA,   g_accA);
    cudaGetSymbolAddress((void**)&accB,   g_accB);
    cudaGetSymbolAddress((void**)&cnt,    g_cnt);
    cudaGetSymbolAddress((void**)&off,    g_off);
    cudaGetSymbolAddress((void**)&cursor, g_cursor);
    cudaGetSymbolAddress((void**)&bsum,   g_bsum);
    cudaGetSymbolAddress((void**)&perm,   g_perm);

    const int FUSED_SMEM = (64 * 68 + 5 * 64 * 64) * sizeof(float);   // 99328
    cudaFuncSetAttribute(rgcn_fused, cudaFuncAttributeMaxDynamicSharedMemorySize, FUSED_SMEM);

    int gemm_blocks = (N + 63) / 64;
    int agg_blocks  = (N + 15) / 16;
    int nchunks     = (N + 1023) / 1024;

    // ---- sort edges by src (once; shared by both layers) ----
    zero_cnt<<<(N + 1023) / 1024, 1024>>>(cnt, N);
    hist<<<(E + 255) / 256, 256>>>(src, cnt, E);
    scanA<<<nchunks, 1024>>>(cnt, off, bsum, N);
    scanB<<<1, 1024>>>(bsum, nchunks);
    scanC<<<nchunks, 1024>>>(off, bsum, cursor, N);
    permute<<<(E + 255) / 256, 256>>>(src, cursor, perm, E);

    // ---- input projection ----
    input_proj<<<(N + 3) / 4, 256>>>(x, Win, bin, h0, N);

    // ---- layer 0 ----
    rgcn_fused<<<gemm_blocks, 256, FUSED_SMEM>>>(h0, 0, Wself0, bases0, bself0, accA, p, N);
    edge_agg<<<agg_blocks, 256>>>(off, perm, tgt, et, coef0, p, accA, N, E);

    // ---- layer 1 (input = relu(accA)) ----
    rgcn_fused<<<gemm_blocks, 256, FUSED_SMEM>>>(accA, 1, Wself1, bases1, bself1, accB, p, N);
    edge_agg<<<agg_blocks, 256>>>(off, perm, tgt, et, coef1, p, accB, N, E);

    // ---- readout (on relu(accB)) ----
    zero_stats<<<1, 64>>>();
    reduce_stats<<<148, 256>>>(accB, N);
    graph_head<<<1, 128>>>(Wr1, br1, Wr2, br2, out, N);

    // ---- node embeddings ----
    for (int half = 0; half < 2; half++)
        gemm64<<<gemm_blocks, 256>>>(accB, 1, Wnp + half * 64, 128, bnp + half * 64,
                                     out + 128 + half * 64, 128, N);
}